// round 9
// baseline (speedup 1.0000x reference)
#include <cuda_runtime.h>
#include <math.h>
#include <stdint.h>

#define BB 4
#define NN 4096
#define DD 1024
#define EE 64
#define CAP 80
#define NTOK (BB*NN)            // 16384
#define EC (EE*CAP)             // 5120
#define COMBINE_OFF ((size_t)NTOK*(size_t)EC)   // 83886080

#define GEMM_BLOCKS 256
#define FILL_BLOCKS 2048
#define FILL_V4_PER_BLOCK 20480    // 41,943,040 float4 / 2048 blocks
#define FILL_V4_PER_THREAD 80      // / 256 threads

// Eigen/XLA-CPU vectorized exp clamps its input at ln(FLT_MIN)
#define EXP_CLAMP_LO (-87.33654785156250f)

// ---------------- scratch (no allocs allowed) ----------------
__device__ float  g_logits[NTOK*EE];
__device__ int    g_idx12 [NTOK];            // idx1 | idx2<<8
__device__ float2 g_gate  [NTOK];            // (g1, g2)
__device__ unsigned short g_pos[2*NTOK];     // [2t]=pos1, [2t+1]=pos2
__device__ double g_psum  [BB*EE];           // sum of probs per (b,e)
__device__ double g_bal;
__device__ double g_zsum;                    // sum of lse over all tokens

// Emulate XLA:CPU FTZ: flush f32 denormals to +0 (bit-level, compiler-proof).
__device__ __forceinline__ float ftz(float v) {
    unsigned u = __float_as_uint(v);
    return ((u & 0x7F800000u) == 0u) ? 0.0f : v;
}

// ---------------- block-specialized: GEMM blocks + zero-fill blocks, one launch ----------------
// Blocks [0,256) compute logits = x @ w (FMA-bound, 16KB smem).
// Blocks [256,2304) stream 671MB of zeros into out (DRAM-bound, 0 smem).
// Co-resident on every SM -> FMA pipe and DRAM write queue stay busy together.
__global__ void gemm_fill_kernel(const float* __restrict__ x,
                                 const float* __restrict__ w,
                                 float* __restrict__ out) {
    int tid = threadIdx.x;

    if (blockIdx.x >= GEMM_BLOCKS) {
        // ---------------- fill branch ----------------
        float4* ov = (float4*)out;
        size_t base = (size_t)(blockIdx.x - GEMM_BLOCKS) * FILL_V4_PER_BLOCK + tid;
        const float4 z4 = make_float4(0.f, 0.f, 0.f, 0.f);
#pragma unroll 8
        for (int i = 0; i < FILL_V4_PER_THREAD; i++)
            __stcs(&ov[base + (size_t)i * 256], z4);
        return;
    }

    // ---------------- GEMM branch ----------------
    __shared__ float xs[64][32];
    __shared__ float ws[32][64];

    if (blockIdx.x == 0) {                 // re-zero per replay, before consumers run
        if (tid < BB*EE) g_psum[tid] = 0.0;
        if (tid == 0) { g_bal = 0.0; g_zsum = 0.0; }
    }

    int tx = tid & 15;
    int ty = tid >> 4;
    int tok0 = blockIdx.x * 64;

    float acc[4][4];
#pragma unroll
    for (int i = 0; i < 4; i++)
#pragma unroll
        for (int j = 0; j < 4; j++) acc[i][j] = 0.f;

    for (int kk = 0; kk < DD; kk += 32) {
#pragma unroll
        for (int r = 0; r < 2; r++) {
            int f = tid + 256 * r;
            int t  = f >> 3, kq = f & 7;
            float4 v = *(const float4*)(x + (size_t)(tok0 + t) * DD + kk + kq * 4);
            *(float4*)&xs[t][kq * 4] = v;
            int k = f >> 4, eq = f & 15;
            float4 u = *(const float4*)(w + (size_t)(kk + k) * EE + eq * 4);
            *(float4*)&ws[k][eq * 4] = u;
        }
        __syncthreads();
#pragma unroll
        for (int k = 0; k < 32; k++) {
            float4 wv = *(float4*)&ws[k][tx * 4];
            float x0 = xs[ty * 4 + 0][k];
            float x1 = xs[ty * 4 + 1][k];
            float x2 = xs[ty * 4 + 2][k];
            float x3 = xs[ty * 4 + 3][k];
            acc[0][0] += x0 * wv.x; acc[0][1] += x0 * wv.y; acc[0][2] += x0 * wv.z; acc[0][3] += x0 * wv.w;
            acc[1][0] += x1 * wv.x; acc[1][1] += x1 * wv.y; acc[1][2] += x1 * wv.z; acc[1][3] += x1 * wv.w;
            acc[2][0] += x2 * wv.x; acc[2][1] += x2 * wv.y; acc[2][2] += x2 * wv.z; acc[2][3] += x2 * wv.w;
            acc[3][0] += x3 * wv.x; acc[3][1] += x3 * wv.y; acc[3][2] += x3 * wv.z; acc[3][3] += x3 * wv.w;
        }
        __syncthreads();
    }
#pragma unroll
    for (int i = 0; i < 4; i++) {
        float4 v = make_float4(acc[i][0], acc[i][1], acc[i][2], acc[i][3]);
        *(float4*)&g_logits[(size_t)(tok0 + ty * 4 + i) * EE + tx * 4] = v;
    }
}

// ---------------- softmax + top-2 + prob-sum + z-loss accumulation ----------------
__global__ void softmax_top2_kernel() {
    __shared__ float accs[64];
    __shared__ double lse8[8];
    int warp = threadIdx.x >> 5;
    int lane = threadIdx.x & 31;
    int token = blockIdx.x * 8 + warp;
    const float* lg = g_logits + (size_t)token * EE;

    if (threadIdx.x < 64) accs[threadIdx.x] = 0.f;
    __syncthreads();

    float v0 = lg[lane];
    float v1 = lg[lane + 32];

    float m = fmaxf(v0, v1);
#pragma unroll
    for (int o = 16; o; o >>= 1) m = fmaxf(m, __shfl_xor_sync(0xffffffffu, m, o));

    float e0 = expf(fmaxf(v0 - m, EXP_CLAMP_LO));
    float e1 = expf(fmaxf(v1 - m, EXP_CLAMP_LO));
    float s = e0 + e1;
#pragma unroll
    for (int o = 16; o; o >>= 1) s += __shfl_xor_sync(0xffffffffu, s, o);

    float p0 = ftz(e0 / s);
    float p1 = ftz(e1 / s);

    atomicAdd(&accs[lane],      p0);
    atomicAdd(&accs[lane + 32], p1);

    unsigned long long k0 = ((unsigned long long)__float_as_uint(p0) << 32) | (unsigned)(63 - lane);
    unsigned long long k1 = ((unsigned long long)__float_as_uint(p1) << 32) | (unsigned)(63 - (lane + 32));

    unsigned long long kt = (k0 > k1) ? k0 : k1;
#pragma unroll
    for (int o = 16; o; o >>= 1) {
        unsigned long long ko = __shfl_xor_sync(0xffffffffu, kt, o);
        if (ko > kt) kt = ko;
    }
    int ri = 63 - (int)(kt & 0x3F);

    unsigned long long q0 = (lane        == ri) ? 0ULL : k0;
    unsigned long long q1 = ((lane + 32) == ri) ? 0ULL : k1;
    unsigned long long kt2 = (q0 > q1) ? q0 : q1;
#pragma unroll
    for (int o = 16; o; o >>= 1) {
        unsigned long long ko = __shfl_xor_sync(0xffffffffu, kt2, o);
        if (ko > kt2) kt2 = ko;
    }
    int ri2 = 63 - (int)(kt2 & 0x3F);

    if (lane == 0) {
        lse8[warp] = (double)m + log((double)s);
        float pv1 = __uint_as_float((unsigned)(kt  >> 32));
        float pv2 = __uint_as_float((unsigned)(kt2 >> 32));
        float denom = pv1 + pv2 + 1e-9f;
        g_idx12[token] = ri | (ri2 << 8);
        g_gate[token] = make_float2(ftz(pv1 / denom), ftz(pv2 / denom));
    }

    __syncthreads();
    if (threadIdx.x == 0) {
        double zs = lse8[0] + lse8[1] + lse8[2] + lse8[3]
                  + lse8[4] + lse8[5] + lse8[6] + lse8[7];
        atomicAdd(&g_zsum, zs);
    }
    if (threadIdx.x < 64) {
        int b = blockIdx.x >> 9;           // 512 blocks per batch
        atomicAdd(&g_psum[b * EE + threadIdx.x], (double)accs[threadIdx.x]);
    }
}

// ---------------- per-(batch, expert) prefix scan ----------------
__device__ __forceinline__ int block_scan_incl(int v, int* sh, int tid, int* total) {
    __syncthreads();
    sh[tid] = v;
    __syncthreads();
#pragma unroll
    for (int o = 1; o < 256; o <<= 1) {
        int t = (tid >= o) ? sh[tid - o] : 0;
        __syncthreads();
        sh[tid] += t;
        __syncthreads();
    }
    int incl = sh[tid];
    *total = sh[255];
    return incl;
}

__global__ void scan_kernel() {
    __shared__ int sh[256];
    int b = blockIdx.x >> 6;
    int e = blockIdx.x & 63;
    int tid = threadIdx.x;
    int base = b * NN;
    int n0 = tid * 16;

    int idx[16];
#pragma unroll
    for (int q = 0; q < 4; q++) {
        int4 v = *(const int4*)&g_idx12[base + n0 + q * 4];
        idx[q*4+0] = v.x; idx[q*4+1] = v.y; idx[q*4+2] = v.z; idx[q*4+3] = v.w;
    }

    int c1 = 0, c2 = 0;
    unsigned m1bits = 0, m2bits = 0;
#pragma unroll
    for (int j = 0; j < 16; j++) {
        if ((idx[j] & 0xFF) == e) { c1++; m1bits |= (1u << j); }
        if ((idx[j] >> 8)   == e) { c2++; m2bits |= (1u << j); }
    }

    int tot1, tot2;
    int incl1 = block_scan_incl(c1, sh, tid, &tot1);
    int incl2 = block_scan_incl(c2, sh, tid, &tot2);
    (void)tot2;

    int off1 = incl1 - c1;
    int off2 = incl2 - c2;
#pragma unroll
    for (int j = 0; j < 16; j++) {
        if ((m1bits >> j) & 1u) { g_pos[2*(base + n0 + j)]     = (unsigned short)off1; off1++; }
        if ((m2bits >> j) & 1u) { g_pos[2*(base + n0 + j) + 1] = (unsigned short)off2; off2++; }
    }

    if (tid == 0) {
        double part = (g_psum[b * EE + e] / (double)NN) * ((double)tot1 / (double)NN);
        atomicAdd(&g_bal, part);
    }
}

// ---------------- scatter nonzeros into the pre-zeroed output + scalars ----------------
__global__ void scatter_kernel(float* __restrict__ out) {
    int token = blockIdx.x * 128 + threadIdx.x;

    int idx12 = g_idx12[token];
    unsigned short p1 = g_pos[2*token];
    unsigned short p2 = g_pos[2*token + 1];
    float2 g = g_gate[token];
    int e1 = idx12 & 0xFF, e2 = idx12 >> 8;
    float v1 = (p1 < CAP) ? g.x : 0.f;
    float v2 = (p2 < CAP) ? g.y : 0.f;

    size_t dbase = (size_t)token * EC;
    if (__float_as_int(v1) != 0) {
        size_t o1 = dbase + e1 * CAP + p1;
        out[o1] = 1.f;
        out[COMBINE_OFF + o1] = v1;
    }
    if (__float_as_int(v2) != 0) {
        size_t o2 = dbase + e2 * CAP + p2;
        out[o2] = 1.f;
        out[COMBINE_OFF + o2] = v2;
    }

    if (blockIdx.x == 0 && threadIdx.x == 0) {
        out[2 * COMBINE_OFF]     = (float)(g_bal * (double)EE / (double)BB);
        out[2 * COMBINE_OFF + 1] = (float)(g_zsum / (double)BB);
    }
}

extern "C" void kernel_launch(void* const* d_in, const int* in_sizes, int n_in,
                              void* d_out, int out_size) {
    const float* x = (const float*)d_in[0];
    const float* w = (const float*)d_in[1];
    float* out = (float*)d_out;

    gemm_fill_kernel<<<GEMM_BLOCKS + FILL_BLOCKS, 256>>>(x, w, out);
    softmax_top2_kernel<<<NTOK / 8, 256>>>();
    scan_kernel<<<BB * EE, 256>>>();
    scatter_kernel<<<NTOK / 128, 128>>>(out);
}

// round 10
// speedup vs baseline: 1.1433x; 1.1433x over previous
#include <cuda_runtime.h>
#include <math.h>
#include <stdint.h>

#define BB 4
#define NN 4096
#define DD 1024
#define EE 64
#define CAP 80
#define NTOK (BB*NN)            // 16384
#define EC (EE*CAP)             // 5120
#define COMBINE_OFF ((size_t)NTOK*(size_t)EC)   // 83886080

#define GEMM_BLOCKS 256
#define FILL_BLOCKS 2048
#define FILL_V4_PER_BLOCK 20480    // 41,943,040 float4 / 2048 blocks
#define FILL_V4_PER_THREAD 80      // / 256 threads

// Eigen/XLA-CPU vectorized exp clamps its input at ln(FLT_MIN)
#define EXP_CLAMP_LO (-87.33654785156250f)

// ---------------- scratch (no allocs allowed) ----------------
__device__ float  g_logits[NTOK*EE];
__device__ int    g_idx12 [NTOK];            // idx1 | idx2<<8
__device__ float2 g_gate  [NTOK];            // (g1, g2)
__device__ unsigned short g_pos[2*NTOK];     // [2t]=pos1, [2t+1]=pos2
__device__ double g_psum  [BB*EE];           // sum of probs per (b,e)
__device__ double g_bal;
__device__ double g_zsum;                    // sum of lse over all tokens

// Emulate XLA:CPU FTZ: flush f32 denormals to +0 (bit-level, compiler-proof).
__device__ __forceinline__ float ftz(float v) {
    unsigned u = __float_as_uint(v);
    return ((u & 0x7F800000u) == 0u) ? 0.0f : v;
}

// ---------------- block-specialized GEMM (pipelined) + zero-fill, one launch ----------------
// GEMM branch: 64 tok x 64 exp tile, k-chunk 64, register double-buffered:
// next tile's LDGs issue BEFORE the ~2000-cycle FMA phase, so inflated DRAM
// latency under concurrent fill-write pressure is hidden.
__global__ void gemm_fill_kernel(const float* __restrict__ x,
                                 const float* __restrict__ w,
                                 float* __restrict__ out) {
    int tid = threadIdx.x;

    if (blockIdx.x >= GEMM_BLOCKS) {
        // ---------------- fill branch ----------------
        float4* ov = (float4*)out;
        size_t base = (size_t)(blockIdx.x - GEMM_BLOCKS) * FILL_V4_PER_BLOCK + tid;
        const float4 z4 = make_float4(0.f, 0.f, 0.f, 0.f);
#pragma unroll 8
        for (int i = 0; i < FILL_V4_PER_THREAD; i++)
            __stcs(&ov[base + (size_t)i * 256], z4);
        return;
    }

    // ---------------- GEMM branch ----------------
    __shared__ float xs[64][64];   // [token][k]
    __shared__ float ws[64][64];   // [k][expert]

    if (blockIdx.x == 0) {                 // re-zero per replay, before consumers run
        if (tid < BB*EE) g_psum[tid] = 0.0;
        if (tid == 0) { g_bal = 0.0; g_zsum = 0.0; }
    }

    int tx = tid & 15;
    int ty = tid >> 4;
    int tok0 = blockIdx.x * 64;

    // both tiles are 64x64: flat float4 id f -> row=f>>4, quad=f&15
    float4 rx[4], rw[4];
#pragma unroll
    for (int r = 0; r < 4; r++) {
        int f = tid + 256 * r;
        int row = f >> 4, q = f & 15;
        rx[r] = *(const float4*)(x + (size_t)(tok0 + row) * DD + q * 4);
        rw[r] = *(const float4*)(w + (size_t)row * EE + q * 4);
    }

    float acc[4][4];
#pragma unroll
    for (int i = 0; i < 4; i++)
#pragma unroll
        for (int j = 0; j < 4; j++) acc[i][j] = 0.f;

    for (int t = 0; t < DD / 64; t++) {
        __syncthreads();                   // previous compute done; smem free
#pragma unroll
        for (int r = 0; r < 4; r++) {
            int f = tid + 256 * r;
            int row = f >> 4, q = f & 15;
            *(float4*)&xs[row][q * 4] = rx[r];
            *(float4*)&ws[row][q * 4] = rw[r];
        }
        __syncthreads();

        if (t + 1 < DD / 64) {             // prefetch next tile into registers;
            int kk = (t + 1) * 64;         // consumed only after the FMA phase
#pragma unroll
            for (int r = 0; r < 4; r++) {
                int f = tid + 256 * r;
                int row = f >> 4, q = f & 15;
                rx[r] = *(const float4*)(x + (size_t)(tok0 + row) * DD + kk + q * 4);
                rw[r] = *(const float4*)(w + (size_t)(kk + row) * EE + q * 4);
            }
        }

#pragma unroll 16
        for (int k = 0; k < 64; k++) {
            float4 wv = *(float4*)&ws[k][tx * 4];
            float x0 = xs[ty * 4 + 0][k];
            float x1 = xs[ty * 4 + 1][k];
            float x2 = xs[ty * 4 + 2][k];
            float x3 = xs[ty * 4 + 3][k];
            acc[0][0] += x0 * wv.x; acc[0][1] += x0 * wv.y; acc[0][2] += x0 * wv.z; acc[0][3] += x0 * wv.w;
            acc[1][0] += x1 * wv.x; acc[1][1] += x1 * wv.y; acc[1][2] += x1 * wv.z; acc[1][3] += x1 * wv.w;
            acc[2][0] += x2 * wv.x; acc[2][1] += x2 * wv.y; acc[2][2] += x2 * wv.z; acc[2][3] += x2 * wv.w;
            acc[3][0] += x3 * wv.x; acc[3][1] += x3 * wv.y; acc[3][2] += x3 * wv.z; acc[3][3] += x3 * wv.w;
        }
    }
#pragma unroll
    for (int i = 0; i < 4; i++) {
        float4 v = make_float4(acc[i][0], acc[i][1], acc[i][2], acc[i][3]);
        *(float4*)&g_logits[(size_t)(tok0 + ty * 4 + i) * EE + tx * 4] = v;
    }
}

// ---------------- softmax + top-2 + prob-sum + z-loss accumulation ----------------
__global__ void softmax_top2_kernel() {
    __shared__ float accs[64];
    __shared__ double lse8[8];
    int warp = threadIdx.x >> 5;
    int lane = threadIdx.x & 31;
    int token = blockIdx.x * 8 + warp;
    const float* lg = g_logits + (size_t)token * EE;

    if (threadIdx.x < 64) accs[threadIdx.x] = 0.f;
    __syncthreads();

    float v0 = lg[lane];
    float v1 = lg[lane + 32];

    float m = fmaxf(v0, v1);
#pragma unroll
    for (int o = 16; o; o >>= 1) m = fmaxf(m, __shfl_xor_sync(0xffffffffu, m, o));

    float e0 = expf(fmaxf(v0 - m, EXP_CLAMP_LO));
    float e1 = expf(fmaxf(v1 - m, EXP_CLAMP_LO));
    float s = e0 + e1;
#pragma unroll
    for (int o = 16; o; o >>= 1) s += __shfl_xor_sync(0xffffffffu, s, o);

    float p0 = ftz(e0 / s);
    float p1 = ftz(e1 / s);

    atomicAdd(&accs[lane],      p0);
    atomicAdd(&accs[lane + 32], p1);

    unsigned long long k0 = ((unsigned long long)__float_as_uint(p0) << 32) | (unsigned)(63 - lane);
    unsigned long long k1 = ((unsigned long long)__float_as_uint(p1) << 32) | (unsigned)(63 - (lane + 32));

    unsigned long long kt = (k0 > k1) ? k0 : k1;
#pragma unroll
    for (int o = 16; o; o >>= 1) {
        unsigned long long ko = __shfl_xor_sync(0xffffffffu, kt, o);
        if (ko > kt) kt = ko;
    }
    int ri = 63 - (int)(kt & 0x3F);

    unsigned long long q0 = (lane        == ri) ? 0ULL : k0;
    unsigned long long q1 = ((lane + 32) == ri) ? 0ULL : k1;
    unsigned long long kt2 = (q0 > q1) ? q0 : q1;
#pragma unroll
    for (int o = 16; o; o >>= 1) {
        unsigned long long ko = __shfl_xor_sync(0xffffffffu, kt2, o);
        if (ko > kt2) kt2 = ko;
    }
    int ri2 = 63 - (int)(kt2 & 0x3F);

    if (lane == 0) {
        lse8[warp] = (double)m + log((double)s);
        float pv1 = __uint_as_float((unsigned)(kt  >> 32));
        float pv2 = __uint_as_float((unsigned)(kt2 >> 32));
        float denom = pv1 + pv2 + 1e-9f;
        g_idx12[token] = ri | (ri2 << 8);
        g_gate[token] = make_float2(ftz(pv1 / denom), ftz(pv2 / denom));
    }

    __syncthreads();
    if (threadIdx.x == 0) {
        double zs = lse8[0] + lse8[1] + lse8[2] + lse8[3]
                  + lse8[4] + lse8[5] + lse8[6] + lse8[7];
        atomicAdd(&g_zsum, zs);
    }
    if (threadIdx.x < 64) {
        int b = blockIdx.x >> 9;           // 512 blocks per batch
        atomicAdd(&g_psum[b * EE + threadIdx.x], (double)accs[threadIdx.x]);
    }
}

// ---------------- per-(batch, expert) prefix scan ----------------
__device__ __forceinline__ int block_scan_incl(int v, int* sh, int tid, int* total) {
    __syncthreads();
    sh[tid] = v;
    __syncthreads();
#pragma unroll
    for (int o = 1; o < 256; o <<= 1) {
        int t = (tid >= o) ? sh[tid - o] : 0;
        __syncthreads();
        sh[tid] += t;
        __syncthreads();
    }
    int incl = sh[tid];
    *total = sh[255];
    return incl;
}

__global__ void scan_kernel() {
    __shared__ int sh[256];
    int b = blockIdx.x >> 6;
    int e = blockIdx.x & 63;
    int tid = threadIdx.x;
    int base = b * NN;
    int n0 = tid * 16;

    int idx[16];
#pragma unroll
    for (int q = 0; q < 4; q++) {
        int4 v = *(const int4*)&g_idx12[base + n0 + q * 4];
        idx[q*4+0] = v.x; idx[q*4+1] = v.y; idx[q*4+2] = v.z; idx[q*4+3] = v.w;
    }

    int c1 = 0, c2 = 0;
    unsigned m1bits = 0, m2bits = 0;
#pragma unroll
    for (int j = 0; j < 16; j++) {
        if ((idx[j] & 0xFF) == e) { c1++; m1bits |= (1u << j); }
        if ((idx[j] >> 8)   == e) { c2++; m2bits |= (1u << j); }
    }

    int tot1, tot2;
    int incl1 = block_scan_incl(c1, sh, tid, &tot1);
    int incl2 = block_scan_incl(c2, sh, tid, &tot2);
    (void)tot2;

    int off1 = incl1 - c1;
    int off2 = incl2 - c2;
#pragma unroll
    for (int j = 0; j < 16; j++) {
        if ((m1bits >> j) & 1u) { g_pos[2*(base + n0 + j)]     = (unsigned short)off1; off1++; }
        if ((m2bits >> j) & 1u) { g_pos[2*(base + n0 + j) + 1] = (unsigned short)off2; off2++; }
    }

    if (tid == 0) {
        double part = (g_psum[b * EE + e] / (double)NN) * ((double)tot1 / (double)NN);
        atomicAdd(&g_bal, part);
    }
}

// ---------------- scatter nonzeros into the pre-zeroed output + scalars ----------------
__global__ void scatter_kernel(float* __restrict__ out) {
    int token = blockIdx.x * 128 + threadIdx.x;

    int idx12 = g_idx12[token];
    unsigned short p1 = g_pos[2*token];
    unsigned short p2 = g_pos[2*token + 1];
    float2 g = g_gate[token];
    int e1 = idx12 & 0xFF, e2 = idx12 >> 8;
    float v1 = (p1 < CAP) ? g.x : 0.f;
    float v2 = (p2 < CAP) ? g.y : 0.f;

    size_t dbase = (size_t)token * EC;
    if (__float_as_int(v1) != 0) {
        size_t o1 = dbase + e1 * CAP + p1;
        out[o1] = 1.f;
        out[COMBINE_OFF + o1] = v1;
    }
    if (__float_as_int(v2) != 0) {
        size_t o2 = dbase + e2 * CAP + p2;
        out[o2] = 1.f;
        out[COMBINE_OFF + o2] = v2;
    }

    if (blockIdx.x == 0 && threadIdx.x == 0) {
        out[2 * COMBINE_OFF]     = (float)(g_bal * (double)EE / (double)BB);
        out[2 * COMBINE_OFF + 1] = (float)(g_zsum / (double)BB);
    }
}

extern "C" void kernel_launch(void* const* d_in, const int* in_sizes, int n_in,
                              void* d_out, int out_size) {
    const float* x = (const float*)d_in[0];
    const float* w = (const float*)d_in[1];
    float* out = (float*)d_out;

    gemm_fill_kernel<<<GEMM_BLOCKS + FILL_BLOCKS, 256>>>(x, w, out);
    softmax_top2_kernel<<<NTOK / 8, 256>>>();
    scan_kernel<<<BB * EE, 256>>>();
    scatter_kernel<<<NTOK / 128, 128>>>(out);
}